// round 11
// baseline (speedup 1.0000x reference)
#include <cuda_runtime.h>
#include <math.h>

typedef unsigned long long u64;
#define Bq 32
#define Dq 128
#define Hq 256
#define Oq 10
#define NCT 36                 // C tile blocks (upper-tri of 8x8 tiles of 32)
#define NKB 4                  // K blocks per batch (g-quarters)
#define NQT 10                 // quarter-tile pairs per batch (upper-tri of 4x4)
#define NPQ (Bq*NQT)           // 320 pair blocks
#define BX_P (NCT)             // 36  : P blocks start
#define BX_K (NCT+Bq)          // 68  : K blocks start
#define BX_Q (BX_K+NKB*Bq)     // 196 : pair blocks start
#define GRID (BX_Q+NPQ)        // 516 total (< 592 resident capacity -> 1 wave)

// Scratch (allocation-free rule: __device__ globals; zero-initialized)
__device__ float g_C[Hq*Hq];
__device__ __align__(16) float g_KT[Bq*Hq*12];   // K transposed: [b][g][o], stride 12
__device__ float g_u[Bq*Hq];
__device__ float g_G2p[Bq][NKB][112];
__device__ float g_M2p[Bq][NKB][112];
__device__ float g_num[Bq*Dq];
__device__ float g_nv[Bq];
__device__ float g_part[Bq*NQT];
__device__ int   g_band[8];          // per-32-row-band completion (target 8)
__device__ int   g_udone[Bq];
__device__ int   g_kq[Bq*4];         // per-quarter K^T published
__device__ int   g_kcnt[Bq];         // K blocks fully done (G2+M2) (target 4)
__device__ int   g_pdone[Bq];
__device__ int   g_cnt[Bq];          // pair partials done (target NQT)
__device__ int   g_all;

__device__ const int QHT[NQT] = {0,0,0,0,1,1,1,2,2,3};
__device__ const int QGT[NQT] = {0,1,2,3,1,2,3,2,3,3};

// ---- f32x2 packed helpers (sm_103a) ----
__device__ __forceinline__ u64 pk2(float x, float y){ u64 r; asm("mov.b64 %0,{%1,%2};" : "=l"(r) : "f"(x),"f"(y)); return r; }
__device__ __forceinline__ u64 fma2(u64 a,u64 b,u64 c){ u64 d; asm("fma.rn.f32x2 %0,%1,%2,%3;" : "=l"(d) : "l"(a),"l"(b),"l"(c)); return d; }
__device__ __forceinline__ void up2(u64 a, float&x, float&y){ asm("mov.b64 {%0,%1},%2;" : "=f"(x),"=f"(y) : "l"(a)); }
__device__ __forceinline__ float hadd2(u64 a){ float x,y; up2(a,x,y); return x+y; }
__device__ __forceinline__ int ldacq(const int* p){
    int v; asm volatile("ld.global.acquire.gpu.b32 %0, [%1];" : "=r"(v) : "l"(p) : "memory"); return v;
}
__device__ __forceinline__ void strel(int* p, int v){
    asm volatile("st.global.release.gpu.b32 [%0], %1;" :: "l"(p), "r"(v) : "memory");
}

__global__ void __launch_bounds__(256, 4)
mega(const float* __restrict__ t,  const float* __restrict__ sb,
     const float* __restrict__ x0, const float* __restrict__ x1,
     const float* __restrict__ W1, const float* __restrict__ b1,
     const float* __restrict__ W2, float* __restrict__ out)
{
    __shared__ __align__(16) float SH[9600];
    __shared__ float sred[8];
    __shared__ float sscale;
    __shared__ int   sflag;
    int tid = threadIdx.x;
    int bx  = blockIdx.x;

    // ========= Phase C: C = W1^T W1 (36 symmetric 32x32 tiles, band release) =========
    if (bx < NCT) {
        int r = bx, ti = 0;
        while (r >= 8 - ti) { r -= 8 - ti; ti++; }
        int tj = ti + r;
        float* shA = SH;            // [128][36]
        float* shB = SH + 4608;     // [128][36]
        for (int i = tid; i < 1024; i += 256) {     // float4 staging
            int d = i >> 3, c4 = (i & 7) * 4;
            *(float4*)(shA + d*36 + c4) = *(const float4*)(W1 + d*Hq + ti*32 + c4);
            *(float4*)(shB + d*36 + c4) = *(const float4*)(W1 + d*Hq + tj*32 + c4);
        }
        __syncthreads();
        int jb = tid & 31, a0 = (tid >> 5) * 4;
        float acc0=0.f, acc1=0.f, acc2=0.f, acc3=0.f;
        #pragma unroll 4
        for (int d = 0; d < Dq; d++) {
            float4 av = *(const float4*)(shA + d*36 + a0);
            float  bv = shB[d*36 + jb];
            acc0 += av.x*bv; acc1 += av.y*bv; acc2 += av.z*bv; acc3 += av.w*bv;
        }
        int h0 = ti*32, g0 = tj*32;
        g_C[(h0+a0+0)*Hq + g0+jb] = acc0;
        g_C[(h0+a0+1)*Hq + g0+jb] = acc1;
        g_C[(h0+a0+2)*Hq + g0+jb] = acc2;
        g_C[(h0+a0+3)*Hq + g0+jb] = acc3;
        if (ti != tj) {
            g_C[(g0+jb)*Hq + h0+a0+0] = acc0;
            g_C[(g0+jb)*Hq + h0+a0+1] = acc1;
            g_C[(g0+jb)*Hq + h0+a0+2] = acc2;
            g_C[(g0+jb)*Hq + h0+a0+3] = acc3;
        }
        __threadfence();
        __syncthreads();
        if (tid == 0) {           // each band i completes when its 8 tiles land
            atomicAdd(&g_band[ti], 1);
            if (ti != tj) atomicAdd(&g_band[tj], 1);
        }
        return;
    }

    // ================= Phase P: 32 C-free per-batch blocks (overlaps C) =================
    if (bx < BX_K) {
        int b = bx - BX_P;
        float2* sxv = (float2*)SH;
        float*  ss  = SH + 256;
        float*  sq  = SH + 512;
        float*  sp  = SH + 768;
        float*  sc  = SH + 1024;

        float tt = t[0];
        float window = 4.f*tt*(1.f-tt);
        if (tid < Dq) {
            float dev = sb[b*Dq + tid];
            float a0v = x0[b*Dq + tid];
            sxv[tid] = make_float2(a0v + tt*(x1[b*Dq+tid]-a0v) + window*dev,
                                   sb[Bq*Dq + b*Dq + tid]);
        }
        __syncthreads();

        u64 zw = pk2(b1[tid], 0.f);
        const u64* sxv64 = (const u64*)sxv;
        #pragma unroll 4
        for (int d = 0; d < Dq; d++) {
            float wv = W1[d*Hq + tid];
            zw = fma2(sxv64[d], pk2(wv,wv), zw);
        }
        float z, w; up2(zw, z, w);
        float th = tanhf(z);
        float s  = 1.f - th*th;
        float u  = -2.f*th*s;
        ss[tid] = s;
        sq[tid] = u*w*w;
        float w2r[Oq];
        #pragma unroll
        for (int o=0;o<Oq;o++) w2r[o] = W2[tid*Oq+o];

        if (tid < 32) {
            float acc = 0.f;
            for (int d = tid; d < Dq; d += 32) { float v = sxv[d].y; acc += v*v; }
            #pragma unroll
            for (int o = 16; o; o >>= 1) acc += __shfl_xor_sync(~0u, acc, o);
            if (tid == 0) g_nv[b] = sqrtf(acc) + 1e-6f;
        }
        __syncthreads();

        int warp = tid>>5, lane = tid&31;
        for (int o = warp; o < Oq; o += 8) {
            float acc = 0.f;
            #pragma unroll
            for (int k = 0; k < 8; k++) { int h = lane + 32*k; acc += W2[h*Oq+o]*sq[h]; }
            #pragma unroll
            for (int off = 16; off; off >>= 1) acc += __shfl_xor_sync(~0u, acc, off);
            if (lane == 0) sc[o] = acc;
        }
        __syncthreads();
        {
            float p = 0.f;
            #pragma unroll
            for (int o=0;o<Oq;o++) p += w2r[o]*sc[o];
            sp[tid] = ss[tid]*p;
        }
        __syncthreads();
        for (int r0 = 0; r0 < 16; r0 += 4) {
            int i0 = warp*16 + r0;
            float a0=0.f,a1=0.f,a2=0.f,a3=0.f;
            #pragma unroll
            for (int k = 0; k < 8; k++) {
                int gg = lane + 32*k;
                float spv = sp[gg];
                a0 += spv*W1[(i0+0)*Hq+gg];
                a1 += spv*W1[(i0+1)*Hq+gg];
                a2 += spv*W1[(i0+2)*Hq+gg];
                a3 += spv*W1[(i0+3)*Hq+gg];
            }
            #pragma unroll
            for (int off = 16; off; off >>= 1) {
                a0 += __shfl_xor_sync(~0u,a0,off); a1 += __shfl_xor_sync(~0u,a1,off);
                a2 += __shfl_xor_sync(~0u,a2,off); a3 += __shfl_xor_sync(~0u,a3,off);
            }
            if (lane == 0) {
                g_num[b*Dq+i0+0]=a0; g_num[b*Dq+i0+1]=a1;
                g_num[b*Dq+i0+2]=a2; g_num[b*Dq+i0+3]=a3;
            }
        }
        __threadfence();
        __syncthreads();
        if (tid == 0) strel(&g_pdone[b], 1);
        return;
    }

    // ===== Phase K: 128 blocks (4/batch). K sweep -> publish+kq -> G2 -> K2 -> M2 =====
    if (bx < BX_Q) {
        int kb = bx - BX_K;
        int b = kb >> 2, quarter = kb & 3, gbase = quarter * 64;
        float* sx    = SH;          // [128]
        float* ssw2  = SH + 256;    // [256][12]  {s*W2, u, f}
        float* spart = SH + 3328;   // [256][12]
        float* sKTc  = SH + 6400;   // [64][12]
        float* sK2c  = SH + 7168;   // [64][12]

        float tt = t[0];
        float window = 4.f*tt*(1.f-tt);
        if (tid < Dq) {
            float dev = sb[b*Dq + tid];
            float a0v = x0[b*Dq + tid];
            sx[tid] = a0v + tt*(x1[b*Dq+tid]-a0v) + window*dev;
        }
        __syncthreads();

        float z0 = b1[tid], z1 = 0.f, z2 = 0.f, z3 = 0.f;
        #pragma unroll 4
        for (int d = 0; d < Dq; d += 4) {
            z0 += sx[d+0]*W1[(d+0)*Hq + tid];
            z1 += sx[d+1]*W1[(d+1)*Hq + tid];
            z2 += sx[d+2]*W1[(d+2)*Hq + tid];
            z3 += sx[d+3]*W1[(d+3)*Hq + tid];
        }
        float z = (z0+z1)+(z2+z3);
        float th = tanhf(z);
        float s  = 1.f - th*th;
        float f  = -2.f*th;
        if (quarter == 0) g_u[b*Hq + tid] = f*s;
        #pragma unroll
        for (int o=0;o<Oq;o++) ssw2[tid*12+o] = s*W2[tid*Oq+o];
        ssw2[tid*12+10] = f*s;
        ssw2[tid*12+11] = f;
        __syncthreads();
        if (quarter == 0 && tid == 0) { __threadfence(); strel(&g_udone[b], 1); }

        // per-warp band wait (warp w's group sweeps h in [64*(w>>1), +64))
        {
            int grp = tid >> 6;
            int b0 = 2*grp;
            if ((tid & 31) == 0) {
                while (ldacq(&g_band[b0]) < 8 || ldacq(&g_band[b0+1]) < 8) {}
            }
            __syncwarp();
        }

        int g = gbase + (tid & 63);
        int hbase = (tid >> 6) * 64;

        // ---- K sweep ----
        {
            float cb[2][16];
            #pragma unroll
            for (int i=0;i<16;i++) cb[0][i] = g_C[(hbase+i)*Hq + g];
            u64 k0=0,k1v=0,k2v=0,k3=0,k4=0;
            #pragma unroll
            for (int ch = 0; ch < 4; ch++) {
                int cur = ch & 1;
                if (ch < 3) {
                    #pragma unroll
                    for (int i=0;i<16;i++) cb[cur^1][i] = g_C[(hbase+(ch+1)*16+i)*Hq + g];
                }
                #pragma unroll
                for (int i=0;i<16;i++) {
                    float c = cb[cur][i];
                    u64 bb = pk2(c,c);
                    const float* row = ssw2 + (hbase+ch*16+i)*12;
                    ulonglong2 p01 = *(const ulonglong2*)(row);
                    ulonglong2 p23 = *(const ulonglong2*)(row + 4);
                    u64 p4 = *(const u64*)(row + 8);
                    k0=fma2(p01.x,bb,k0); k1v=fma2(p01.y,bb,k1v);
                    k2v=fma2(p23.x,bb,k2v); k3=fma2(p23.y,bb,k3); k4=fma2(p4,bb,k4);
                }
            }
            u64* pd = (u64*)(spart + tid*12);
            pd[0]=k0; pd[1]=k1v; pd[2]=k2v; pd[3]=k3; pd[4]=k4;
        }
        __syncthreads();
        if (tid < 64) {   // combine + publish K^T
            float kv[Oq];
            #pragma unroll
            for (int o=0;o<Oq;o++) {
                kv[o] = spart[tid*12+o] + spart[(tid+64)*12+o]
                      + spart[(tid+128)*12+o] + spart[(tid+192)*12+o];
                sKTc[tid*12+o] = kv[o];
            }
            u64* ktd = (u64*)(g_KT + (b*Hq + gbase + tid)*12);
            #pragma unroll
            for (int i=0;i<5;i++) ktd[i] = pk2(kv[2*i], kv[2*i+1]);
        }
        __threadfence();
        __syncthreads();
        if (tid == 0) strel(&g_kq[b*4 + quarter], 1);    // release Q early

        // ---- G2 partial ----
        if (tid < Oq*Oq) {
            int o = tid/Oq, p = tid%Oq;
            float accA = 0.f, accB = 0.f;
            #pragma unroll 4
            for (int gg = 0; gg < 64; gg += 2) {
                accA += sKTc[gg*12+o]     * ssw2[(gbase+gg)*12+p];
                accB += sKTc[(gg+1)*12+o] * ssw2[(gbase+gg+1)*12+p];
            }
            g_G2p[b][quarter][tid] = accA + accB;
        }
        __syncthreads();

        // ---- K2 sweep (off Q's critical path): weight u_h*C^2 = f_h*C^2 on s*W2 rows ----
        {
            float cb[2][16];
            #pragma unroll
            for (int i=0;i<16;i++) cb[0][i] = g_C[(hbase+i)*Hq + g];
            u64 k0=0,k1v=0,k2v=0,k3=0,k4=0;
            #pragma unroll
            for (int ch = 0; ch < 4; ch++) {
                int cur = ch & 1;
                if (ch < 3) {
                    #pragma unroll
                    for (int i=0;i<16;i++) cb[cur^1][i] = g_C[(hbase+(ch+1)*16+i)*Hq + g];
                }
                #pragma unroll
                for (int i=0;i<16;i++) {
                    int h = hbase + ch*16 + i;
                    float c = cb[cur][i];
                    float m = c*c*ssw2[h*12+11];
                    u64 bb = pk2(m,m);
                    const float* row = ssw2 + h*12;
                    ulonglong2 p01 = *(const ulonglong2*)(row);
                    ulonglong2 p23 = *(const ulonglong2*)(row + 4);
                    u64 p4 = *(const u64*)(row + 8);
                    k0=fma2(p01.x,bb,k0); k1v=fma2(p01.y,bb,k1v);
                    k2v=fma2(p23.x,bb,k2v); k3=fma2(p23.y,bb,k3); k4=fma2(p4,bb,k4);
                }
            }
            u64* pd = (u64*)(spart + tid*12);
            pd[0]=k0; pd[1]=k1v; pd[2]=k2v; pd[3]=k3; pd[4]=k4;
        }
        __syncthreads();
        if (tid < 64) {
            #pragma unroll
            for (int o=0;o<Oq;o++)
                sK2c[tid*12+o] = spart[tid*12+o] + spart[(tid+64)*12+o]
                               + spart[(tid+128)*12+o] + spart[(tid+192)*12+o];
        }
        __syncthreads();
        // ---- M2 partial: M2[o,p] = sum_g K2[o,g]*(u_g W2[g,p]) ----
        if (tid < Oq*Oq) {
            int o = tid/Oq, p = tid%Oq;
            float accA = 0.f, accB = 0.f;
            #pragma unroll 4
            for (int gg = 0; gg < 64; gg += 2) {
                accA += sK2c[gg*12+o]     * ssw2[(gbase+gg)*12+p]   * ssw2[(gbase+gg)*12+11];
                accB += sK2c[(gg+1)*12+o] * ssw2[(gbase+gg+1)*12+p] * ssw2[(gbase+gg+1)*12+11];
            }
            g_M2p[b][quarter][tid] = accA + accB;
        }
        __threadfence();
        __syncthreads();
        if (tid == 0) atomicAdd(&g_kcnt[b], 1);
        return;
    }

    // ===== Phase Q: 320 quarter-tile blocks (64x64), term2 only, 16-h loops =====
    {
        int pb = bx - BX_Q;
        int b = pb / NQT, tt = pb - b*NQT;
        int qh = QHT[tt], qg = QGT[tt];
        int h0 = qh*64, g0 = qg*64;
        bool diag = (qh == qg);
        int g = g0 + (tid & 63);
        int hsub = tid >> 6;
        int hbase = h0 + hsub*16;
        float* sWU = SH;         // [64][12] u_h-scaled W2 rows
        float* sKT = SH + 768;   // [64][12] K[:,h]

        // ---- stage A: no dependencies ----
        float w2g[Oq];
        #pragma unroll
        for (int o=0;o<Oq;o++) w2g[o] = W2[g*Oq+o];
        if (tt == 0 && tid < Dq)
            out[b*Dq + tid] = sb[Bq*Dq + b*Dq + tid];   // velocity half
        float w2h[Oq];
        if (tid >= 128 && tid < 192) {
            int h = h0 + (tid - 128);
            #pragma unroll
            for (int o=0;o<Oq;o++) w2h[o] = W2[h*Oq+o];
        }

        // ---- waits: u + the two K quarters this tile touches ----
        if (tid == 0) {
            while (ldacq(&g_udone[b]) == 0) {}
            while (ldacq(&g_kq[b*4 + qh]) == 0) {}
            while (ldacq(&g_kq[b*4 + qg]) == 0) {}
        }
        __syncthreads();
        float u_g = g_u[b*Hq + g];
        if (tid >= 128 && tid < 192) {
            int hh = tid - 128;
            float uh = g_u[b*Hq + h0 + hh];
            #pragma unroll
            for (int o=0;o<Oq;o++) sWU[hh*12+o] = uh*w2h[o];
        } else if (tid >= 192) {
            int hh = tid - 192;
            const u64* src = (const u64*)(g_KT + (b*Hq + h0 + hh)*12);
            u64* dst = (u64*)(sKT + hh*12);
            #pragma unroll
            for (int i=0;i<5;i++) dst[i] = src[i];
        }
        u64 kcp[5];
        {
            const u64* kt = (const u64*)(g_KT + (b*Hq + g)*12);
            #pragma unroll
            for (int i=0;i<5;i++) kcp[i] = kt[i];
        }
        float c16[16];
        #pragma unroll
        for (int i=0;i<16;i++) c16[i] = g_C[(hbase+i)*Hq + g];
        __syncthreads();

        u64 w2p[5];
        #pragma unroll
        for (int i=0;i<5;i++) w2p[i] = pk2(w2g[2*i], w2g[2*i+1]);

        u64 accr = 0;
        #pragma unroll
        for (int i=0;i<16;i++) {
            int hl = hsub*16 + i;
            const float* rowa = sWU + hl*12;
            const float* rowb = sKT + hl*12;
            ulonglong2 a01 = *(const ulonglong2*)(rowa);
            ulonglong2 a23 = *(const ulonglong2*)(rowa + 4);
            u64 a4 = *(const u64*)(rowa + 8);
            ulonglong2 b01 = *(const ulonglong2*)(rowb);
            ulonglong2 b23 = *(const ulonglong2*)(rowb + 4);
            u64 b4 = *(const u64*)(rowb + 8);
            u64 r2=0, s2=0;
            r2 = fma2(a01.x, kcp[0], r2); r2 = fma2(a01.y, kcp[1], r2);
            r2 = fma2(a23.x, kcp[2], r2); r2 = fma2(a23.y, kcp[3], r2);
            r2 = fma2(a4,    kcp[4], r2);
            s2 = fma2(b01.x, w2p[0], s2); s2 = fma2(b01.y, w2p[1], s2);
            s2 = fma2(b23.x, w2p[2], s2); s2 = fma2(b23.y, w2p[3], s2);
            s2 = fma2(b4,    w2p[4], s2);
            float m = c16[i] * hadd2(s2);
            if (diag) {
                int hg = hbase + i;
                m *= (g > hg) ? 2.f : ((g == hg) ? 1.f : 0.f);
            }
            accr = fma2(r2, pk2(m,m), accr);
        }
        float acc = hadd2(accr) * u_g;
        if (!diag) acc *= 2.f;

        #pragma unroll
        for (int off = 16; off; off >>= 1) acc += __shfl_xor_sync(~0u, acc, off);
        if ((tid&31) == 0) sred[tid>>5] = acc;
        __syncthreads();
        if (tid == 0) {
            float ttl = 0.f;
            #pragma unroll
            for (int i=0;i<8;i++) ttl += sred[i];
            g_part[b*NQT + tt] = ttl;
            __threadfence();
            int old = atomicAdd(&g_cnt[b], 1);
            sflag = (old == NQT-1);
        }
        __syncthreads();
        if (sflag) {   // finalize: T1 = sum(G2 o M2) (fixed order), n2 = 2*(T1 + term2)
            if (tid == 0) {
                while (ldacq(&g_pdone[b]) == 0) {}
                while (ldacq(&g_kcnt[b]) < NKB) {}
            }
            __syncthreads();
            float v = 0.f;
            if (tid < Oq*Oq) {
                float G2s = g_G2p[b][0][tid] + g_G2p[b][1][tid]
                          + g_G2p[b][2][tid] + g_G2p[b][3][tid];
                float M2s = g_M2p[b][0][tid] + g_M2p[b][1][tid]
                          + g_M2p[b][2][tid] + g_M2p[b][3][tid];
                v = G2s * M2s;
            }
            #pragma unroll
            for (int off = 16; off; off >>= 1) v += __shfl_xor_sync(~0u, v, off);
            if ((tid&31) == 0) sred[tid>>5] = v;
            __syncthreads();
            if (tid == 0) {
                float T1 = sred[0] + sred[1] + sred[2] + sred[3];
                float n2 = T1;
                #pragma unroll
                for (int k=0;k<NQT;k++) n2 += g_part[b*NQT + k];
                n2 *= 2.f;
                float nF = sqrtf(fmaxf(n2, 0.f)) + 1e-6f;
                sscale = -1.f/(nF * g_nv[b]);
                g_cnt[b]  = 0;   // reset for replay
                g_kcnt[b] = 0;
            }
            __syncthreads();
            if (tid < Dq)
                out[Bq*Dq + b*Dq + tid] = g_num[b*Dq+tid]*sscale - 0.1f*sb[b*Dq+tid];
        }
        if (tid == 0) {   // global epilogue: reset shared flags for replay
            int old = atomicAdd(&g_all, 1);
            if (old == NPQ-1) {
                #pragma unroll
                for (int i=0;i<8;i++) g_band[i] = 0;
                for (int i=0;i<Bq*4;i++) g_kq[i] = 0;
                #pragma unroll
                for (int i=0;i<Bq;i++) { g_pdone[i] = 0; g_udone[i] = 0; }
                g_all = 0;
            }
        }
    }
}

extern "C" void kernel_launch(void* const* d_in, const int* in_sizes, int n_in,
                              void* d_out, int out_size) {
    const float* t  = (const float*)d_in[0];
    const float* sb = (const float*)d_in[1];
    const float* x0 = (const float*)d_in[2];
    const float* x1 = (const float*)d_in[3];
    const float* W1 = (const float*)d_in[4];
    const float* b1 = (const float*)d_in[5];
    const float* W2 = (const float*)d_in[6];
    float* out = (float*)d_out;

    mega<<<GRID, 256>>>(t, sb, x0, x1, W1, b1, W2, out);
}

// round 12
// speedup vs baseline: 1.0950x; 1.0950x over previous
#include <cuda_runtime.h>
#include <math.h>

typedef unsigned long long u64;
#define Bq 32
#define Dq 128
#define Hq 256
#define Oq 10
#define NCT 144               // C tile blocks: 32x8 tiles, tj3 >= 4*ti
#define NKB 4                 // K blocks per batch (g-quarters)
#define NS  8                 // h-splits per batch in pair phase
#define NP  (Bq*NS)           // 256 pair blocks
#define BX_P (NCT)            // 144 : P blocks start
#define BX_K (NCT+Bq)         // 176 : K blocks start
#define BX_Q (BX_K+NKB*Bq)    // 304 : pair blocks start
#define GRID (BX_Q+NP)        // 560 total (< 592 resident capacity -> 1 wave)

// Scratch (allocation-free rule: __device__ globals; zero-initialized)
__device__ float g_C[Hq*Hq];
__device__ __align__(16) float g_KT[Bq*Hq*12];   // K transposed: [b][g][o], stride 12
__device__ float g_u[Bq*Hq];
__device__ float g_G2p[Bq][NKB][112];
__device__ float g_num[Bq*Dq];
__device__ float g_nv[Bq];
__device__ float g_part[Bq*NS];
__device__ int   g_band[8];          // per-32-row-band completion counters (target 32)
__device__ int   g_udone[Bq];
__device__ int   g_kqc[Bq];          // K^T quarters published (target 4) — early release
__device__ int   g_kcnt[Bq];         // K blocks fully done incl. G2 (target 4)
__device__ int   g_pdone[Bq];
__device__ int   g_cnt[Bq];
__device__ int   g_all;

// ---- f32x2 packed helpers (sm_103a) ----
__device__ __forceinline__ u64 pk2(float x, float y){ u64 r; asm("mov.b64 %0,{%1,%2};" : "=l"(r) : "f"(x),"f"(y)); return r; }
__device__ __forceinline__ u64 fma2(u64 a,u64 b,u64 c){ u64 d; asm("fma.rn.f32x2 %0,%1,%2,%3;" : "=l"(d) : "l"(a),"l"(b),"l"(c)); return d; }
__device__ __forceinline__ void up2(u64 a, float&x, float&y){ asm("mov.b64 {%0,%1},%2;" : "=f"(x),"=f"(y) : "l"(a)); }
__device__ __forceinline__ float hadd2(u64 a){ float x,y; up2(a,x,y); return x+y; }
__device__ __forceinline__ int ldacq(const int* p){
    int v; asm volatile("ld.global.acquire.gpu.b32 %0, [%1];" : "=r"(v) : "l"(p) : "memory"); return v;
}
__device__ __forceinline__ void strel(int* p, int v){
    asm volatile("st.global.release.gpu.b32 [%0], %1;" :: "l"(p), "r"(v) : "memory");
}

__global__ void __launch_bounds__(256, 4)
mega(const float* __restrict__ t,  const float* __restrict__ sb,
     const float* __restrict__ x0, const float* __restrict__ x1,
     const float* __restrict__ W1, const float* __restrict__ b1,
     const float* __restrict__ W2, float* __restrict__ out)
{
    __shared__ __align__(16) float SH[9600];
    __shared__ float sred[8];
    __shared__ float sscale;
    __shared__ int   sflag;
    int tid = threadIdx.x;
    int bx  = blockIdx.x;

    // ========= Phase C: C = W1^T W1, 144 blocks of 32x8 tiles (tj3 >= 4*ti) =========
    if (bx < NCT) {
        int r = bx, ti = 0;
        while (r >= 32 - 4*ti) { r -= 32 - 4*ti; ti++; }
        int tj3 = 4*ti + r;          // 8-col block index
        float* shA = SH;             // [128][36]
        float* shB = SH + 4608;      // [128][12]
        for (int i = tid; i < 1024; i += 256) {     // stage A: 128x32 via float4
            int d = i >> 3, c4 = (i & 7) * 4;
            *(float4*)(shA + d*36 + c4) = *(const float4*)(W1 + d*Hq + ti*32 + c4);
        }
        {                                           // stage B: 128x8 via float4
            int d = tid >> 1, c4 = (tid & 1) * 4;
            *(float4*)(shB + d*12 + c4) = *(const float4*)(W1 + d*Hq + tj3*8 + c4);
        }
        __syncthreads();
        int jb = tid & 7, a = tid >> 3;    // 8 cols x 32 rows, 1 output/thread
        float acc0=0.f, acc1=0.f, acc2=0.f, acc3=0.f;
        #pragma unroll 4
        for (int d = 0; d < Dq; d += 4) {
            acc0 += shA[(d+0)*36 + a] * shB[(d+0)*12 + jb];
            acc1 += shA[(d+1)*36 + a] * shB[(d+1)*12 + jb];
            acc2 += shA[(d+2)*36 + a] * shB[(d+2)*12 + jb];
            acc3 += shA[(d+3)*36 + a] * shB[(d+3)*12 + jb];
        }
        float acc = (acc0+acc1)+(acc2+acc3);
        int h = ti*32 + a, g = tj3*8 + jb;
        g_C[h*Hq + g] = acc;
        g_C[g*Hq + h] = acc;   // mirror: duplicate writes are bitwise-identical
        __threadfence();
        __syncthreads();
        if (tid == 0) {        // band release: each band completes at count 32
            atomicAdd(&g_band[ti], 1);
            int bj = tj3 >> 2;
            if (bj != ti) atomicAdd(&g_band[bj], 1);
        }
        return;
    }

    // ================= Phase P: 32 C-free per-batch blocks (overlaps C) =================
    if (bx < BX_K) {
        int b = bx - BX_P;
        float2* sxv = (float2*)SH;        // [128] (x,v)
        float*  ss  = SH + 256;
        float*  sq  = SH + 512;           // u*w^2
        float*  sp  = SH + 768;
        float*  sc  = SH + 1024;          // [16]

        float tt = t[0];
        float window = 4.f*tt*(1.f-tt);
        if (tid < Dq) {
            float dev = sb[b*Dq + tid];
            float a0v = x0[b*Dq + tid];
            sxv[tid] = make_float2(a0v + tt*(x1[b*Dq+tid]-a0v) + window*dev,
                                   sb[Bq*Dq + b*Dq + tid]);
        }
        __syncthreads();

        u64 zw = pk2(b1[tid], 0.f);
        const u64* sxv64 = (const u64*)sxv;
        #pragma unroll 4
        for (int d = 0; d < Dq; d++) {
            float wv = W1[d*Hq + tid];
            zw = fma2(sxv64[d], pk2(wv,wv), zw);
        }
        float z, w; up2(zw, z, w);
        float th = tanhf(z);
        float s  = 1.f - th*th;
        float u  = -2.f*th*s;
        ss[tid] = s;
        sq[tid] = u*w*w;
        float w2r[Oq];
        #pragma unroll
        for (int o=0;o<Oq;o++) w2r[o] = W2[tid*Oq+o];

        if (tid < 32) {   // ||v||
            float acc = 0.f;
            for (int d = tid; d < Dq; d += 32) { float v = sxv[d].y; acc += v*v; }
            #pragma unroll
            for (int o = 16; o; o >>= 1) acc += __shfl_xor_sync(~0u, acc, o);
            if (tid == 0) g_nv[b] = sqrtf(acc) + 1e-6f;
        }
        __syncthreads();

        // c_o = sum_h W2[h][o] u_h w_h^2   (warp per o)
        int warp = tid>>5, lane = tid&31;
        for (int o = warp; o < Oq; o += 8) {
            float acc = 0.f;
            #pragma unroll
            for (int k = 0; k < 8; k++) { int h = lane + 32*k; acc += W2[h*Oq+o]*sq[h]; }
            #pragma unroll
            for (int off = 16; off; off >>= 1) acc += __shfl_xor_sync(~0u, acc, off);
            if (lane == 0) sc[o] = acc;
        }
        __syncthreads();
        {
            float p = 0.f;
            #pragma unroll
            for (int o=0;o<Oq;o++) p += w2r[o]*sc[o];
            sp[tid] = ss[tid]*p;
        }
        __syncthreads();
        // num_i = sum_g sp_g W1[i][g]  (warp-per-row, 4 concurrent rows)
        for (int r0 = 0; r0 < 16; r0 += 4) {
            int i0 = warp*16 + r0;
            float a0=0.f,a1=0.f,a2=0.f,a3=0.f;
            #pragma unroll
            for (int k = 0; k < 8; k++) {
                int gg = lane + 32*k;
                float spv = sp[gg];
                a0 += spv*W1[(i0+0)*Hq+gg];
                a1 += spv*W1[(i0+1)*Hq+gg];
                a2 += spv*W1[(i0+2)*Hq+gg];
                a3 += spv*W1[(i0+3)*Hq+gg];
            }
            #pragma unroll
            for (int off = 16; off; off >>= 1) {
                a0 += __shfl_xor_sync(~0u,a0,off); a1 += __shfl_xor_sync(~0u,a1,off);
                a2 += __shfl_xor_sync(~0u,a2,off); a3 += __shfl_xor_sync(~0u,a3,off);
            }
            if (lane == 0) {
                g_num[b*Dq+i0+0]=a0; g_num[b*Dq+i0+1]=a1;
                g_num[b*Dq+i0+2]=a2; g_num[b*Dq+i0+3]=a3;
            }
        }
        __threadfence();
        __syncthreads();
        if (tid == 0) strel(&g_pdone[b], 1);
        return;
    }

    // ========= Phase K: 128 blocks (4/batch, g-quarters), per-warp band waits =========
    if (bx < BX_Q) {
        int kb = bx - BX_K;
        int b = kb >> 2, quarter = kb & 3, gbase = quarter * 64;
        float* sx    = SH;          // [128]
        float* ssw2  = SH + 256;    // [256][12]
        float* spart = SH + 3328;   // [256][12] partial K
        float* sKTc  = SH + 6400;   // [64][12] combined K (this g-quarter)

        float tt = t[0];
        float window = 4.f*tt*(1.f-tt);
        if (tid < Dq) {
            float dev = sb[b*Dq + tid];
            float a0v = x0[b*Dq + tid];
            sx[tid] = a0v + tt*(x1[b*Dq+tid]-a0v) + window*dev;
        }
        __syncthreads();

        // z with 4 independent accumulator chains (overlaps C phase)
        float z0 = b1[tid], z1 = 0.f, z2 = 0.f, z3 = 0.f;
        #pragma unroll 4
        for (int d = 0; d < Dq; d += 4) {
            z0 += sx[d+0]*W1[(d+0)*Hq + tid];
            z1 += sx[d+1]*W1[(d+1)*Hq + tid];
            z2 += sx[d+2]*W1[(d+2)*Hq + tid];
            z3 += sx[d+3]*W1[(d+3)*Hq + tid];
        }
        float z = (z0+z1)+(z2+z3);
        float th = tanhf(z);
        float s  = 1.f - th*th;
        if (quarter == 0) g_u[b*Hq + tid] = -2.f*th*s;
        #pragma unroll
        for (int o=0;o<Oq;o++) ssw2[tid*12+o] = s*W2[tid*Oq+o];
        __syncthreads();
        // early-u release (overlapped by the band waits below)
        if (quarter == 0 && tid == 0) { __threadfence(); strel(&g_udone[b], 1); }

        // per-warp wait on only the two h-bands this warp's group sweeps
        {
            int grp = tid >> 6;           // h-range [64*grp, 64*grp+64)
            int b0 = 2*grp;
            if ((tid & 31) == 0) {
                while (ldacq(&g_band[b0]) < 32 || ldacq(&g_band[b0+1]) < 32) {}
            }
            __syncwarp();
        }

        // partial K: thread -> g = gbase+(tid&63), h in [hbase,hbase+64), double-buffered
        {
            int g = gbase + (tid & 63);
            int hbase = (tid >> 6) * 64;
            float cb[2][16];
            #pragma unroll
            for (int i=0;i<16;i++) cb[0][i] = g_C[(hbase+i)*Hq + g];
            u64 k0=0,k1v=0,k2v=0,k3=0,k4=0;
            #pragma unroll
            for (int ch = 0; ch < 4; ch++) {
                int cur = ch & 1;
                if (ch < 3) {
                    #pragma unroll
                    for (int i=0;i<16;i++) cb[cur^1][i] = g_C[(hbase+(ch+1)*16+i)*Hq + g];
                }
                #pragma unroll
                for (int i=0;i<16;i++) {
                    float c = cb[cur][i];
                    u64 bb = pk2(c,c);
                    const float* row = ssw2 + (hbase+ch*16+i)*12;
                    ulonglong2 p01 = *(const ulonglong2*)(row);
                    ulonglong2 p23 = *(const ulonglong2*)(row + 4);
                    u64 p4 = *(const u64*)(row + 8);
                    k0=fma2(p01.x,bb,k0); k1v=fma2(p01.y,bb,k1v);
                    k2v=fma2(p23.x,bb,k2v); k3=fma2(p23.y,bb,k3); k4=fma2(p4,bb,k4);
                }
            }
            u64* pd = (u64*)(spart + tid*12);
            pd[0]=k0; pd[1]=k1v; pd[2]=k2v; pd[3]=k3; pd[4]=k4;
        }
        __syncthreads();
        if (tid < 64) {   // combine 4 h-quarters (fixed order), publish K^T
            float kv[Oq];
            #pragma unroll
            for (int o=0;o<Oq;o++) {
                kv[o] = spart[tid*12+o] + spart[(tid+64)*12+o]
                      + spart[(tid+128)*12+o] + spart[(tid+192)*12+o];
                sKTc[tid*12+o] = kv[o];
            }
            u64* ktd = (u64*)(g_KT + (b*Hq + gbase + tid)*12);
            #pragma unroll
            for (int i=0;i<5;i++) ktd[i] = pk2(kv[2*i], kv[2*i+1]);
        }
        __threadfence();
        __syncthreads();
        if (tid == 0) atomicAdd(&g_kqc[b], 1);   // EARLY release: K^T published

        // G2 partial over this g-quarter (chain length 64, 2 accumulators)
        if (tid < Oq*Oq) {
            int o = tid/Oq, p = tid%Oq;
            float accA = 0.f, accB = 0.f;
            #pragma unroll 4
            for (int gg = 0; gg < 64; gg += 2) {
                accA += sKTc[gg*12+o]     * ssw2[(gbase+gg)*12+p];
                accB += sKTc[(gg+1)*12+o] * ssw2[(gbase+gg+1)*12+p];
            }
            g_G2p[b][quarter][tid] = accA + accB;
        }
        __threadfence();
        __syncthreads();
        if (tid == 0) atomicAdd(&g_kcnt[b], 1);   // full release incl. G2
        return;
    }

    // ===== Phase Q: 256 pair blocks — y-factorized qq (no pre-loop G2 dependency) =====
    {
        int pb = bx - BX_Q;
        int b = pb >> 3, split = pb & (NS-1);
        int h0 = split * 32;
        int g = tid;
        float* sWU  = SH;         // [32][12] W2 row + u_h at [10]
        float* sKTp = SH + 384;   // [32][12]
        float* sG2  = SH + 768;   // [10][12] padded G2 (pads zero)

        bool active = (g >= h0);  // warp-uniform (h0 multiple of 32)

        // ---- stage A: no dependencies ----
        float w2g[Oq];
        #pragma unroll
        for (int o=0;o<Oq;o++) w2g[o] = W2[g*Oq+o];
        if (split == 0 && tid < Dq)
            out[b*Dq + tid] = sb[Bq*Dq + b*Dq + tid];   // velocity half
        if (tid >= 128 && tid < 160) {
            int hh = tid - 128, h = h0 + hh;
            #pragma unroll
            for (int o=0;o<Oq;o++) sWU[hh*12+o] = W2[h*Oq+o];
        }

        // ---- stage B: u available early (from K quarter-0's z) ----
        if (tid == 0) { while (ldacq(&g_udone[b]) == 0) {} }
        __syncthreads();
        float u_g = g_u[b*Hq + g];
        if (tid >= 128 && tid < 160) {
            int hh = tid - 128;
            sWU[hh*12+10] = g_u[b*Hq + h0 + hh];
        }

        // ---- stage C: K^T published (G2 NOT needed yet) ----
        if (tid == 0) { while (ldacq(&g_kqc[b]) < NKB) {} }
        __syncthreads();
        if (tid >= 128 && tid < 160) {
            int hh = tid - 128;
            const u64* src = (const u64*)(g_KT + (b*Hq + h0 + hh)*12);
            u64* dst = (u64*)(sKTp + hh*12);
            #pragma unroll
            for (int i=0;i<5;i++) dst[i] = src[i];
        }
        u64 kcp[5];
        if (active) {
            const u64* kt = (const u64*)(g_KT + (b*Hq + g)*12);
            #pragma unroll
            for (int i=0;i<5;i++) kcp[i] = kt[i];
        }
        __syncthreads();

        u64 y2[5] = {0,0,0,0,0};   // y[o] = sum_h u_h c^2 W2[h,o]
        u64 accr = 0;
        if (active) {
            u64 w2p[5];
            #pragma unroll
            for (int i=0;i<5;i++) w2p[i] = pk2(w2g[2*i], w2g[2*i+1]);

            // main loop: 4 chunks of 8, double-buffered C loads
            float cbA[8], cbB[8];
            #pragma unroll
            for (int i=0;i<8;i++) cbA[i] = g_C[(h0+i)*Hq + g];
            #pragma unroll
            for (int ch = 0; ch < 4; ch++) {
                float* cur = (ch & 1) ? cbB : cbA;
                float* nxt = (ch & 1) ? cbA : cbB;
                if (ch < 3) {
                    #pragma unroll
                    for (int i=0;i<8;i++) nxt[i] = g_C[(h0+(ch+1)*8+i)*Hq + g];
                }
                #pragma unroll
                for (int i=0;i<8;i++) {
                    int hh = ch*8 + i;
                    const float* rowa = sWU  + hh*12;
                    const float* rowb = sKTp + hh*12;
                    ulonglong2 a01 = *(const ulonglong2*)(rowa);
                    ulonglong2 a23 = *(const ulonglong2*)(rowa + 4);
                    u64 a4 = *(const u64*)(rowa + 8);
                    ulonglong2 b01 = *(const ulonglong2*)(rowb);
                    ulonglong2 b23 = *(const ulonglong2*)(rowb + 4);
                    u64 b4 = *(const u64*)(rowb + 8);
                    u64 r2=0, s2=0;
                    r2 = fma2(a01.x, kcp[0], r2); r2 = fma2(a01.y, kcp[1], r2);
                    r2 = fma2(a23.x, kcp[2], r2); r2 = fma2(a23.y, kcp[3], r2);
                    r2 = fma2(a4,    kcp[4], r2);
                    s2 = fma2(b01.x, w2p[0], s2); s2 = fma2(b01.y, w2p[1], s2);
                    s2 = fma2(b23.x, w2p[2], s2); s2 = fma2(b23.y, w2p[3], s2);
                    s2 = fma2(b4,    w2p[4], s2);
                    float hs = hadd2(s2);
                    float uh = sWU[hh*12+10];
                    float cc = cur[i];
                    float m0 = uh*cc;
                    float mc = m0*cc;
                    float mh = m0*hs;
                    u64 mc2 = pk2(mc,mc);
                    y2[0] = fma2(a01.x, mc2, y2[0]);
                    y2[1] = fma2(a01.y, mc2, y2[1]);
                    y2[2] = fma2(a23.x, mc2, y2[2]);
                    y2[3] = fma2(a23.y, mc2, y2[3]);
                    y2[4] = fma2(a4,    mc2, y2[4]);
                    accr  = fma2(r2, pk2(mh,mh), accr);
                }
            }
        }

        // ---- post-loop: G2 now certainly ready (K's G2 stage overlapped our loop) ----
        if (tid == 0) { while (ldacq(&g_kcnt[b]) < NKB) {} }
        __syncthreads();
        if (tid < 120) {   // padded [10][12] G2 sum, pads zeroed
            int o = tid / 12, p = tid - 12*o;
            float v = 0.f;
            if (p < 10) {
                int idx = o*10 + p;
                v = g_G2p[b][0][idx] + g_G2p[b][1][idx]
                  + g_G2p[b][2][idx] + g_G2p[b][3][idx];
            }
            sG2[tid] = v;
        }
        __syncthreads();

        float acc = 0.f;
        if (active) {
            // z[o] = (G2 w2g)[o]; qq = y . z
            u64 w2p[5];
            #pragma unroll
            for (int i=0;i<5;i++) w2p[i] = pk2(w2g[2*i], w2g[2*i+1]);
            u64 qacc = 0;
            #pragma unroll
            for (int j=0;j<5;j++) {
                const u64* r0 = (const u64*)(sG2 + (2*j)*12);
                const u64* r1 = (const u64*)(sG2 + (2*j+1)*12);
                u64 z0=0, z1=0;
                #pragma unroll
                for (int k=0;k<5;k++) { z0 = fma2(r0[k], w2p[k], z0); z1 = fma2(r1[k], w2p[k], z1); }
                qacc = fma2(y2[j], pk2(hadd2(z0), hadd2(z1)), qacc);
            }
            float wt = (g < h0 + 32) ? 1.f : 2.f;   // diag tile x1, upper tiles x2
            acc = (hadd2(qacc) + hadd2(accr)) * u_g * wt;
        }
        #pragma unroll
        for (int off = 16; off; off >>= 1) acc += __shfl_xor_sync(~0u, acc, off);
        if ((tid&31) == 0) sred[tid>>5] = acc;
        __syncthreads();
        if (tid == 0) {
            float ttl = 0.f;
            #pragma unroll
            for (int i=0;i<8;i++) ttl += sred[i];
            g_part[b*NS + split] = ttl;
            __threadfence();
            int old = atomicAdd(&g_cnt[b], 1);
            sflag = (old == NS-1);
        }
        __syncthreads();
        if (sflag) {   // per-batch finalize (fixed-order sums — deterministic)
            if (tid == 0) {
                while (ldacq(&g_pdone[b]) == 0) {}
                __threadfence();
                float n2 = 0.f;
                #pragma unroll
                for (int k=0;k<NS;k++) n2 += g_part[b*NS + k];
                n2 *= 2.f;
                float nF = sqrtf(fmaxf(n2, 0.f)) + 1e-6f;
                sscale = -1.f/(nF * g_nv[b]);
                g_cnt[b]  = 0;   // reset for replay
                g_kcnt[b] = 0;
                g_kqc[b]  = 0;
            }
            __syncthreads();
            if (tid < Dq)
                out[Bq*Dq + b*Dq + tid] = g_num[b*Dq+tid]*sscale - 0.1f*sb[b*Dq+tid];
        }
        if (tid == 0) {   // global epilogue: reset shared flags for replay
            int old = atomicAdd(&g_all, 1);
            if (old == NP-1) {
                #pragma unroll
                for (int i=0;i<8;i++) g_band[i] = 0;
                #pragma unroll
                for (int i=0;i<Bq;i++) { g_pdone[i] = 0; g_udone[i] = 0; }
                g_all = 0;
            }
        }
    }
}

extern "C" void kernel_launch(void* const* d_in, const int* in_sizes, int n_in,
                              void* d_out, int out_size) {
    const float* t  = (const float*)d_in[0];
    const float* sb = (const float*)d_in[1];
    const float* x0 = (const float*)d_in[2];
    const float* x1 = (const float*)d_in[3];
    const float* W1 = (const float*)d_in[4];
    const float* b1 = (const float*)d_in[5];
    const float* W2 = (const float*)d_in[6];
    float* out = (float*)d_out;

    mega<<<GRID, 256>>>(t, sb, x0, x1, W1, b1, W2, out);
}

// round 13
// speedup vs baseline: 1.1208x; 1.0236x over previous
#include <cuda_runtime.h>
#include <math.h>

typedef unsigned long long u64;
#define Bq 32
#define Dq 128
#define Hq 256
#define Oq 10
#define NCT 144               // C tile blocks: 32x8 tiles, tj3 >= 4*ti
#define NKB 4                 // K blocks per batch (g-quarters)
#define NS  8                 // h-splits per batch in pair phase
#define NP  (Bq*NS)           // 256 pair blocks
#define BX_P (NCT)            // 144 : P blocks start
#define BX_K (NCT+Bq)         // 176 : K blocks start
#define BX_Q (BX_K+NKB*Bq)    // 304 : pair blocks start
#define GRID (BX_Q+NP)        // 560 total (< 592 resident capacity -> 1 wave)

// Scratch (allocation-free rule: __device__ globals; zero-initialized)
__device__ float g_C[Hq*Hq];
__device__ __align__(16) float g_KT[Bq*Hq*12];   // K transposed: [b][g][o], stride 12
__device__ float g_u[Bq*Hq];
__device__ float g_G2p[Bq][NKB][112];
__device__ float g_num[Bq*Dq];
__device__ float g_nv[Bq];
__device__ float g_part[Bq*NS];
__device__ int   g_band[8];          // per-32-row-band completion counters (target 32)
__device__ int   g_udone[Bq];
__device__ int   g_kqc[Bq];          // K^T quarters published (target 4) — early release
__device__ int   g_kcnt[Bq];         // K blocks fully done incl. G2 (target 4)
__device__ int   g_pdone[Bq];
__device__ int   g_cnt[Bq];
__device__ int   g_all;

// ---- f32x2 packed helpers (sm_103a) ----
__device__ __forceinline__ u64 pk2(float x, float y){ u64 r; asm("mov.b64 %0,{%1,%2};" : "=l"(r) : "f"(x),"f"(y)); return r; }
__device__ __forceinline__ u64 fma2(u64 a,u64 b,u64 c){ u64 d; asm("fma.rn.f32x2 %0,%1,%2,%3;" : "=l"(d) : "l"(a),"l"(b),"l"(c)); return d; }
__device__ __forceinline__ void up2(u64 a, float&x, float&y){ asm("mov.b64 {%0,%1},%2;" : "=f"(x),"=f"(y) : "l"(a)); }
__device__ __forceinline__ float hadd2(u64 a){ float x,y; up2(a,x,y); return x+y; }
__device__ __forceinline__ int ldacq(const int* p){
    int v; asm volatile("ld.global.acquire.gpu.b32 %0, [%1];" : "=r"(v) : "l"(p) : "memory"); return v;
}
__device__ __forceinline__ void strel(int* p, int v){
    asm volatile("st.global.release.gpu.b32 [%0], %1;" :: "l"(p), "r"(v) : "memory");
}

__global__ void __launch_bounds__(256, 4)
mega(const float* __restrict__ t,  const float* __restrict__ sb,
     const float* __restrict__ x0, const float* __restrict__ x1,
     const float* __restrict__ W1, const float* __restrict__ b1,
     const float* __restrict__ W2, float* __restrict__ out)
{
    __shared__ __align__(16) float SH[9600];
    __shared__ float sred[8];
    __shared__ float sscale;
    __shared__ int   sflag;
    int tid = threadIdx.x;
    int bx  = blockIdx.x;

    // ========= Phase C: C = W1^T W1, 144 blocks of 32x8 tiles (tj3 >= 4*ti) =========
    if (bx < NCT) {
        int r = bx, ti = 0;
        while (r >= 32 - 4*ti) { r -= 32 - 4*ti; ti++; }
        int tj3 = 4*ti + r;          // 8-col block index
        float* shA = SH;             // [128][36]
        float* shB = SH + 4608;      // [128][12]
        for (int i = tid; i < 1024; i += 256) {     // stage A: 128x32 via float4
            int d = i >> 3, c4 = (i & 7) * 4;
            *(float4*)(shA + d*36 + c4) = *(const float4*)(W1 + d*Hq + ti*32 + c4);
        }
        {                                           // stage B: 128x8 via float4
            int d = tid >> 1, c4 = (tid & 1) * 4;
            *(float4*)(shB + d*12 + c4) = *(const float4*)(W1 + d*Hq + tj3*8 + c4);
        }
        __syncthreads();
        int jb = tid & 7, a = tid >> 3;    // 8 cols x 32 rows, 1 output/thread
        float acc0=0.f, acc1=0.f, acc2=0.f, acc3=0.f;
        #pragma unroll 4
        for (int d = 0; d < Dq; d += 4) {
            acc0 += shA[(d+0)*36 + a] * shB[(d+0)*12 + jb];
            acc1 += shA[(d+1)*36 + a] * shB[(d+1)*12 + jb];
            acc2 += shA[(d+2)*36 + a] * shB[(d+2)*12 + jb];
            acc3 += shA[(d+3)*36 + a] * shB[(d+3)*12 + jb];
        }
        float acc = (acc0+acc1)+(acc2+acc3);
        int h = ti*32 + a, g = tj3*8 + jb;
        g_C[h*Hq + g] = acc;
        g_C[g*Hq + h] = acc;   // mirror: duplicate writes are bitwise-identical
        __threadfence();
        __syncthreads();
        if (tid == 0) {        // band release: each band completes at count 32
            atomicAdd(&g_band[ti], 1);
            int bj = tj3 >> 2;
            if (bj != ti) atomicAdd(&g_band[bj], 1);
        }
        return;
    }

    // ================= Phase P: 32 C-free per-batch blocks (overlaps C) =================
    if (bx < BX_K) {
        int b = bx - BX_P;
        float2* sxv = (float2*)SH;        // [128] (x,v)
        float*  ss  = SH + 256;
        float*  sq  = SH + 512;           // u*w^2
        float*  sp  = SH + 768;
        float*  sc  = SH + 1024;          // [16]

        float tt = t[0];
        float window = 4.f*tt*(1.f-tt);
        if (tid < Dq) {
            float dev = sb[b*Dq + tid];
            float a0v = x0[b*Dq + tid];
            sxv[tid] = make_float2(a0v + tt*(x1[b*Dq+tid]-a0v) + window*dev,
                                   sb[Bq*Dq + b*Dq + tid]);
        }
        __syncthreads();

        u64 zw = pk2(b1[tid], 0.f);
        const u64* sxv64 = (const u64*)sxv;
        #pragma unroll 4
        for (int d = 0; d < Dq; d++) {
            float wv = W1[d*Hq + tid];
            zw = fma2(sxv64[d], pk2(wv,wv), zw);
        }
        float z, w; up2(zw, z, w);
        float th = tanhf(z);
        float s  = 1.f - th*th;
        float u  = -2.f*th*s;
        ss[tid] = s;
        sq[tid] = u*w*w;
        float w2r[Oq];
        #pragma unroll
        for (int o=0;o<Oq;o++) w2r[o] = W2[tid*Oq+o];

        if (tid < 32) {   // ||v||
            float acc = 0.f;
            for (int d = tid; d < Dq; d += 32) { float v = sxv[d].y; acc += v*v; }
            #pragma unroll
            for (int o = 16; o; o >>= 1) acc += __shfl_xor_sync(~0u, acc, o);
            if (tid == 0) g_nv[b] = sqrtf(acc) + 1e-6f;
        }
        __syncthreads();

        // c_o = sum_h W2[h][o] u_h w_h^2   (warp per o)
        int warp = tid>>5, lane = tid&31;
        for (int o = warp; o < Oq; o += 8) {
            float acc = 0.f;
            #pragma unroll
            for (int k = 0; k < 8; k++) { int h = lane + 32*k; acc += W2[h*Oq+o]*sq[h]; }
            #pragma unroll
            for (int off = 16; off; off >>= 1) acc += __shfl_xor_sync(~0u, acc, off);
            if (lane == 0) sc[o] = acc;
        }
        __syncthreads();
        {
            float p = 0.f;
            #pragma unroll
            for (int o=0;o<Oq;o++) p += w2r[o]*sc[o];
            sp[tid] = ss[tid]*p;
        }
        __syncthreads();
        // num_i = sum_g sp_g W1[i][g]  (warp-per-row, 4 concurrent rows)
        for (int r0 = 0; r0 < 16; r0 += 4) {
            int i0 = warp*16 + r0;
            float a0=0.f,a1=0.f,a2=0.f,a3=0.f;
            #pragma unroll
            for (int k = 0; k < 8; k++) {
                int gg = lane + 32*k;
                float spv = sp[gg];
                a0 += spv*W1[(i0+0)*Hq+gg];
                a1 += spv*W1[(i0+1)*Hq+gg];
                a2 += spv*W1[(i0+2)*Hq+gg];
                a3 += spv*W1[(i0+3)*Hq+gg];
            }
            #pragma unroll
            for (int off = 16; off; off >>= 1) {
                a0 += __shfl_xor_sync(~0u,a0,off); a1 += __shfl_xor_sync(~0u,a1,off);
                a2 += __shfl_xor_sync(~0u,a2,off); a3 += __shfl_xor_sync(~0u,a3,off);
            }
            if (lane == 0) {
                g_num[b*Dq+i0+0]=a0; g_num[b*Dq+i0+1]=a1;
                g_num[b*Dq+i0+2]=a2; g_num[b*Dq+i0+3]=a3;
            }
        }
        __threadfence();
        __syncthreads();
        if (tid == 0) strel(&g_pdone[b], 1);
        return;
    }

    // ========= Phase K: 128 blocks (4/batch, g-quarters), per-warp band waits =========
    if (bx < BX_Q) {
        int kb = bx - BX_K;
        int b = kb >> 2, quarter = kb & 3, gbase = quarter * 64;
        float* sx    = SH;          // [128]
        float* ssw2  = SH + 256;    // [256][12]
        float* spart = SH + 3328;   // [256][12] partial K
        float* sKTc  = SH + 6400;   // [64][12] combined K (this g-quarter)

        float tt = t[0];
        float window = 4.f*tt*(1.f-tt);
        if (tid < Dq) {
            float dev = sb[b*Dq + tid];
            float a0v = x0[b*Dq + tid];
            sx[tid] = a0v + tt*(x1[b*Dq+tid]-a0v) + window*dev;
        }
        __syncthreads();

        // z with 4 independent accumulator chains (overlaps C phase)
        float z0 = b1[tid], z1 = 0.f, z2 = 0.f, z3 = 0.f;
        #pragma unroll 4
        for (int d = 0; d < Dq; d += 4) {
            z0 += sx[d+0]*W1[(d+0)*Hq + tid];
            z1 += sx[d+1]*W1[(d+1)*Hq + tid];
            z2 += sx[d+2]*W1[(d+2)*Hq + tid];
            z3 += sx[d+3]*W1[(d+3)*Hq + tid];
        }
        float z = (z0+z1)+(z2+z3);
        float th = tanhf(z);
        float s  = 1.f - th*th;
        if (quarter == 0) g_u[b*Hq + tid] = -2.f*th*s;
        #pragma unroll
        for (int o=0;o<Oq;o++) ssw2[tid*12+o] = s*W2[tid*Oq+o];
        __syncthreads();
        // early-u release (overlapped by the band waits below)
        if (quarter == 0 && tid == 0) { __threadfence(); strel(&g_udone[b], 1); }

        // per-warp wait on only the two h-bands this warp's group sweeps
        {
            int grp = tid >> 6;           // h-range [64*grp, 64*grp+64)
            int b0 = 2*grp;
            if ((tid & 31) == 0) {
                while (ldacq(&g_band[b0]) < 32 || ldacq(&g_band[b0+1]) < 32) {}
            }
            __syncwarp();
        }

        // partial K: thread -> g = gbase+(tid&63), h in [hbase,hbase+64), double-buffered
        {
            int g = gbase + (tid & 63);
            int hbase = (tid >> 6) * 64;
            float cb[2][16];
            #pragma unroll
            for (int i=0;i<16;i++) cb[0][i] = g_C[(hbase+i)*Hq + g];
            u64 k0=0,k1v=0,k2v=0,k3=0,k4=0;
            #pragma unroll
            for (int ch = 0; ch < 4; ch++) {
                int cur = ch & 1;
                if (ch < 3) {
                    #pragma unroll
                    for (int i=0;i<16;i++) cb[cur^1][i] = g_C[(hbase+(ch+1)*16+i)*Hq + g];
                }
                #pragma unroll
                for (int i=0;i<16;i++) {
                    float c = cb[cur][i];
                    u64 bb = pk2(c,c);
                    const float* row = ssw2 + (hbase+ch*16+i)*12;
                    ulonglong2 p01 = *(const ulonglong2*)(row);
                    ulonglong2 p23 = *(const ulonglong2*)(row + 4);
                    u64 p4 = *(const u64*)(row + 8);
                    k0=fma2(p01.x,bb,k0); k1v=fma2(p01.y,bb,k1v);
                    k2v=fma2(p23.x,bb,k2v); k3=fma2(p23.y,bb,k3); k4=fma2(p4,bb,k4);
                }
            }
            u64* pd = (u64*)(spart + tid*12);
            pd[0]=k0; pd[1]=k1v; pd[2]=k2v; pd[3]=k3; pd[4]=k4;
        }
        __syncthreads();
        if (tid < 64) {   // combine 4 h-quarters (fixed order), publish K^T
            float kv[Oq];
            #pragma unroll
            for (int o=0;o<Oq;o++) {
                kv[o] = spart[tid*12+o] + spart[(tid+64)*12+o]
                      + spart[(tid+128)*12+o] + spart[(tid+192)*12+o];
                sKTc[tid*12+o] = kv[o];
            }
            u64* ktd = (u64*)(g_KT + (b*Hq + gbase + tid)*12);
            #pragma unroll
            for (int i=0;i<5;i++) ktd[i] = pk2(kv[2*i], kv[2*i+1]);
        }
        __threadfence();
        __syncthreads();
        if (tid == 0) atomicAdd(&g_kqc[b], 1);   // EARLY release: K^T published

        // G2 partial over this g-quarter (chain length 64, 2 accumulators)
        if (tid < Oq*Oq) {
            int o = tid/Oq, p = tid%Oq;
            float accA = 0.f, accB = 0.f;
            #pragma unroll 4
            for (int gg = 0; gg < 64; gg += 2) {
                accA += sKTc[gg*12+o]     * ssw2[(gbase+gg)*12+p];
                accB += sKTc[(gg+1)*12+o] * ssw2[(gbase+gg+1)*12+p];
            }
            g_G2p[b][quarter][tid] = accA + accB;
        }
        __threadfence();
        __syncthreads();
        if (tid == 0) atomicAdd(&g_kcnt[b], 1);   // full release incl. G2
        return;
    }

    // ===== Phase Q: 256 pair blocks — staged waits: band->cbA, kqc->KT, kcnt->G2 =====
    {
        int pb = bx - BX_Q;
        int b = pb >> 3, split = pb & (NS-1);
        int h0 = split * 32;
        int g = tid;
        float* sWU  = SH;         // [32][12] W2 row + u_h at [10]
        float* sKTp = SH + 384;   // [32][12]
        float* sG2  = SH + 768;   // [10][12] padded, pads zero

        bool active = (g >= h0);  // warp-uniform (h0 multiple of 32)

        // ---- stage A: no dependencies ----
        float w2g[Oq];
        #pragma unroll
        for (int o=0;o<Oq;o++) w2g[o] = W2[g*Oq+o];
        if (split == 0 && tid < Dq)
            out[b*Dq + tid] = sb[Bq*Dq + b*Dq + tid];   // velocity half
        if (tid >= 128 && tid < 160) {
            int hh = tid - 128, h = h0 + hh;
            #pragma unroll
            for (int o=0;o<Oq;o++) sWU[hh*12+o] = W2[h*Oq+o];
        }

        // ---- stage B: u available early (from K quarter-0's z) ----
        if (tid == 0) { while (ldacq(&g_udone[b]) == 0) {} }
        __syncthreads();
        float u_g = g_u[b*Hq + g];
        if (tid >= 128 && tid < 160) {
            int hh = tid - 128;
            sWU[hh*12+10] = g_u[b*Hq + h0 + hh];
        }

        // ---- stage B2: C band 'split' ready -> prefetch first C chunk ----
        if (tid == 0) { while (ldacq(&g_band[split]) < 32) {} }
        __syncthreads();
        float cbA[8], cbB[8];
        #pragma unroll
        for (int i=0;i<8;i++) cbA[i] = g_C[(h0+i)*Hq + g];

        // ---- stage C1: K^T published (loads overlap K's G2 stage) ----
        if (tid == 0) { while (ldacq(&g_kqc[b]) < NKB) {} }
        __syncthreads();
        if (tid >= 128 && tid < 160) {
            int hh = tid - 128;
            const u64* src = (const u64*)(g_KT + (b*Hq + h0 + hh)*12);
            u64* dst = (u64*)(sKTp + hh*12);
            #pragma unroll
            for (int i=0;i<5;i++) dst[i] = src[i];
        }
        u64 kcp[5];
        if (active) {
            const u64* kt = (const u64*)(g_KT + (b*Hq + g)*12);
            #pragma unroll
            for (int i=0;i<5;i++) kcp[i] = kt[i];
        }

        // ---- stage C2: G2 partials ready ----
        if (tid == 0) { while (ldacq(&g_kcnt[b]) < NKB) {} }
        __syncthreads();
        if (tid < 120) {   // padded [10][12] G2 sum, pads zeroed
            int o = tid / 12, p = tid - 12*o;
            float v = 0.f;
            if (p < 10) {
                int idx = o*10 + p;
                v = g_G2p[b][0][idx] + g_G2p[b][1][idx]
                  + g_G2p[b][2][idx] + g_G2p[b][3][idx];
            }
            sG2[tid] = v;
        }
        __syncthreads();

        float acc = 0.f;
        if (active) {
            u64 w2p[5];
            #pragma unroll
            for (int i=0;i<5;i++) w2p[i] = pk2(w2g[2*i], w2g[2*i+1]);
            // wgp[j] = packed (G2 w2g) pair — vectorized matvec
            u64 wgp[5];
            #pragma unroll
            for (int j=0;j<5;j++) {
                const u64* r0 = (const u64*)(sG2 + (2*j)*12);
                const u64* r1 = (const u64*)(sG2 + (2*j+1)*12);
                u64 z0=0, z1=0;
                #pragma unroll
                for (int k=0;k<5;k++) { z0 = fma2(r0[k], w2p[k], z0); z1 = fma2(r1[k], w2p[k], z1); }
                wgp[j] = pk2(hadd2(z0), hadd2(z1));
            }

            // main loop: 4 chunks of 8, double-buffered C loads, vector accumulators
            u64 accq = 0, accr = 0;
            #pragma unroll
            for (int ch = 0; ch < 4; ch++) {
                float* cur = (ch & 1) ? cbB : cbA;
                float* nxt = (ch & 1) ? cbA : cbB;
                if (ch < 3) {
                    #pragma unroll
                    for (int i=0;i<8;i++) nxt[i] = g_C[(h0+(ch+1)*8+i)*Hq + g];
                }
                #pragma unroll
                for (int i=0;i<8;i++) {
                    int hh = ch*8 + i;
                    const float* rowa = sWU  + hh*12;
                    const float* rowb = sKTp + hh*12;
                    ulonglong2 a01 = *(const ulonglong2*)(rowa);
                    ulonglong2 a23 = *(const ulonglong2*)(rowa + 4);
                    u64 a4 = *(const u64*)(rowa + 8);
                    ulonglong2 b01 = *(const ulonglong2*)(rowb);
                    ulonglong2 b23 = *(const ulonglong2*)(rowb + 4);
                    u64 b4 = *(const u64*)(rowb + 8);
                    u64 q2=0, r2=0, s2=0;
                    q2 = fma2(a01.x, wgp[0], q2); q2 = fma2(a01.y, wgp[1], q2);
                    q2 = fma2(a23.x, wgp[2], q2); q2 = fma2(a23.y, wgp[3], q2);
                    q2 = fma2(a4,    wgp[4], q2);
                    r2 = fma2(a01.x, kcp[0], r2); r2 = fma2(a01.y, kcp[1], r2);
                    r2 = fma2(a23.x, kcp[2], r2); r2 = fma2(a23.y, kcp[3], r2);
                    r2 = fma2(a4,    kcp[4], r2);
                    s2 = fma2(b01.x, w2p[0], s2); s2 = fma2(b01.y, w2p[1], s2);
                    s2 = fma2(b23.x, w2p[2], s2); s2 = fma2(b23.y, w2p[3], s2);
                    s2 = fma2(b4,    w2p[4], s2);
                    float hs = hadd2(s2);
                    float uh = sWU[hh*12+10];
                    float cc = cur[i];
                    float m0 = uh*cc;
                    float mc = m0*cc;
                    float mh = m0*hs;
                    accq = fma2(q2, pk2(mc,mc), accq);
                    accr = fma2(r2, pk2(mh,mh), accr);
                }
            }
            float wt = (g < h0 + 32) ? 1.f : 2.f;   // diag tile x1, upper tiles x2
            acc = (hadd2(accq) + hadd2(accr)) * u_g * wt;
        }
        #pragma unroll
        for (int off = 16; off; off >>= 1) acc += __shfl_xor_sync(~0u, acc, off);
        if ((tid&31) == 0) sred[tid>>5] = acc;
        __syncthreads();
        if (tid == 0) {
            float ttl = 0.f;
            #pragma unroll
            for (int i=0;i<8;i++) ttl += sred[i];
            g_part[b*NS + split] = ttl;
            __threadfence();
            int old = atomicAdd(&g_cnt[b], 1);
            sflag = (old == NS-1);
        }
        __syncthreads();
        if (sflag) {   // per-batch finalize (fixed-order sums — deterministic)
            if (tid == 0) {
                while (ldacq(&g_pdone[b]) == 0) {}
                __threadfence();
                float n2 = 0.f;
                #pragma unroll
                for (int k=0;k<NS;k++) n2 += g_part[b*NS + k];
                n2 *= 2.f;
                float nF = sqrtf(fmaxf(n2, 0.f)) + 1e-6f;
                sscale = -1.f/(nF * g_nv[b]);
                g_cnt[b]  = 0;   // reset for replay
                g_kcnt[b] = 0;
                g_kqc[b]  = 0;
            }
            __syncthreads();
            if (tid < Dq)
                out[Bq*Dq + b*Dq + tid] = g_num[b*Dq+tid]*sscale - 0.1f*sb[b*Dq+tid];
        }
        if (tid == 0) {   // global epilogue: reset shared flags for replay
            int old = atomicAdd(&g_all, 1);
            if (old == NP-1) {
                #pragma unroll
                for (int i=0;i<8;i++) g_band[i] = 0;
                #pragma unroll
                for (int i=0;i<Bq;i++) { g_pdone[i] = 0; g_udone[i] = 0; }
                g_all = 0;
            }
        }
    }
}

extern "C" void kernel_launch(void* const* d_in, const int* in_sizes, int n_in,
                              void* d_out, int out_size) {
    const float* t  = (const float*)d_in[0];
    const float* sb = (const float*)d_in[1];
    const float* x0 = (const float*)d_in[2];
    const float* x1 = (const float*)d_in[3];
    const float* W1 = (const float*)d_in[4];
    const float* b1 = (const float*)d_in[5];
    const float* W2 = (const float*)d_in[6];
    float* out = (float*)d_out;

    mega<<<GRID, 256>>>(t, sb, x0, x1, W1, b1, W2, out);
}